// round 14
// baseline (speedup 1.0000x reference)
#include <cuda_runtime.h>
#include <cstdint>

#define NB 16
#define NC 512
#define NHW 4096
#define KDIM 512

// ---------------------------------------------------------------- scratch
__device__ float g_xT[(size_t)NB * NHW * NC];    // B-fragment layout (n=hw,k=c)
__device__ float g_qk[(size_t)NB * 128 * NHW];   // row-major
__device__ float g_v[(size_t)NB * NC * NHW];     // row-major
__device__ float g_attn[(size_t)NB * 8 * 64 * 64];
__device__ float g_mid[(size_t)NB * NC * NHW];   // A-fragment layout, tf32
__device__ float g_Wqk[128 * NC];                // A-fragment layout
__device__ float g_Wv32[NC * NC];                // A-fragment layout
__device__ float g_Wo32[NC * NC];                // B-fragment layout
__device__ float g_bqk[128];

__device__ __forceinline__ float f2tf(float f) {
    uint32_t o; asm("cvt.rna.tf32.f32 %0, %1;" : "=r"(o) : "f"(f));
    return __uint_as_float(o);
}

// A-fragment-major: 16m x 8k blocks, ordered [M128][kb8][mb16][lane][slot]
__device__ __forceinline__ uint32_t idxA(uint32_t m, uint32_t k) {
    return ((((m >> 7) * (KDIM / 8) + (k >> 3)) * 8 + ((m & 127) >> 4)) * 32
            + (((m & 7) << 2) | (k & 3))) * 4
           + (((m >> 3) & 1) | (((k >> 2) & 1) << 1));
}
// B-fragment-major: 8n x 16k blocks, ordered [N128][kb16][nb8][lane][slot]
__device__ __forceinline__ uint32_t idxB(uint32_t n, uint32_t k) {
    return ((((n >> 7) * (KDIM / 16) + (k >> 4)) * 16 + ((n & 127) >> 3)) * 32
            + (((n & 7) << 2) | (k & 3))) * 4
           + ((k >> 2) & 3);
}

#define CP16(dst, src) asm volatile("cp.async.cg.shared.global [%0], [%1], 16;" :: "r"(dst), "l"(src) : "memory")
#define CP_COMMIT()    asm volatile("cp.async.commit_group;" ::: "memory")
#define CP_WAIT2()     asm volatile("cp.async.wait_group 2;" ::: "memory")
#define CP_WAIT1()     asm volatile("cp.async.wait_group 1;" ::: "memory")
#define CP_WAIT0()     asm volatile("cp.async.wait_group 0;" ::: "memory")

__device__ __forceinline__ uint32_t smem_u32(const void* p) {
    uint32_t a;
    asm("{ .reg .u64 t; cvta.to.shared.u64 t, %1; cvt.u32.u64 %0, t; }" : "=r"(a) : "l"(p));
    return a;
}

#define MMA_TF32(acc, a0, a1, a2, a3, b0, b1) \
    asm volatile("mma.sync.aligned.m16n8k8.row.col.f32.tf32.tf32.f32 " \
        "{%0,%1,%2,%3},{%4,%5,%6,%7},{%8,%9},{%0,%1,%2,%3};" \
        : "+f"((acc)[0]), "+f"((acc)[1]), "+f"((acc)[2]), "+f"((acc)[3]) \
        : "r"(a0), "r"(a1), "r"(a2), "r"(a3), "r"(b0), "r"(b1))

// ---------------------------------------------------------------------------
// Big-tile GEMM: CTA 256m x 128n, warp tile 64x64 (8 warps), BK=32,
// 4-stage cp.async, ONE barrier per iter (prefetch distance 3).
// C[m][n] = sum_k A[m][k]*B[n][k] + bias (m if !BIASN else n).
// ---------------------------------------------------------------------------
#define BIG_STAGE_B 49152                 // A 32KB + B 16KB
#define BIG_SMEM (4 * BIG_STAGE_B)        // 192 KB

template <bool BIASN>
__global__ __launch_bounds__(256, 1) void gemm_big(
    const float* __restrict__ A, size_t sAb,
    const float* __restrict__ B, size_t sBb,
    const float* __restrict__ bias,
    float* __restrict__ C, size_t sCb, int ldc)
{
    extern __shared__ __align__(16) float sm[];
    const uint32_t smb = smem_u32(sm);
    const int b  = blockIdx.z;
    const int n0 = blockIdx.x * 128;
    const int m0 = blockIdx.y * 256;
    const float* Ag = A + (size_t)b * sAb + (size_t)(m0 >> 7) * 65536;
    const float* Bg = B + (size_t)b * sBb + (size_t)(n0 >> 7) * 65536;

    const int t = threadIdx.x, lane = t & 31, w = t >> 5;
    const int wy = w & 3, wx = w >> 2;
    const int blk = wy >> 1, mb0 = (wy & 1) * 4;
    const int q = lane >> 2, s = lane & 3;

    float acc[4][8][4] = {};

    auto fill = [&](int buf, int it) {
        const int ko = it * 32;
        const float* a0 = Ag + (ko >> 3) * 1024;
        const float* a1 = a0 + 65536;
        const float* bb = Bg + (ko >> 4) * 2048;
        uint32_t d = smb + buf * BIG_STAGE_B + t * 16;
#pragma unroll
        for (int i = 0; i < 4; i++) CP16(d + i * 4096,         a0 + t * 4 + i * 1024);
#pragma unroll
        for (int i = 0; i < 4; i++) CP16(d + 16384 + i * 4096, a1 + t * 4 + i * 1024);
#pragma unroll
        for (int i = 0; i < 4; i++) CP16(d + 32768 + i * 4096, bb + t * 4 + i * 1024);
        CP_COMMIT();
    };

    fill(0, 0); fill(1, 1); fill(2, 2);

    for (int it = 0; it < 16; it++) {
        const int buf = it & 3;
        if (it == 15) CP_WAIT0();
        else if (it == 14) CP_WAIT1();
        else CP_WAIT2();
        __syncthreads();                  // publishes group it; all done compute it-1
        if (it <= 12) fill((it + 3) & 3, it + 3);

        const float4* At = reinterpret_cast<const float4*>(sm) + buf * 3072;
        const float4* Bt = At + 2048;
#pragma unroll
        for (int kp = 0; kp < 2; kp++) {
            float4 bf[8];
#pragma unroll
            for (int nj = 0; nj < 8; nj++)
                bf[nj] = Bt[(kp * 16 + wx * 8 + nj) * 32 + lane];
#pragma unroll
            for (int kkl = 0; kkl < 2; kkl++) {
                const int kb = kp * 2 + kkl;
                float4 af[4];
#pragma unroll
                for (int mi = 0; mi < 4; mi++)
                    af[mi] = At[blk * 1024 + (kb * 8 + mb0 + mi) * 32 + lane];
#pragma unroll
                for (int nj = 0; nj < 8; nj++) {
                    uint32_t b0 = __float_as_uint(kkl ? bf[nj].z : bf[nj].x);
                    uint32_t b1 = __float_as_uint(kkl ? bf[nj].w : bf[nj].y);
#pragma unroll
                    for (int mi = 0; mi < 4; mi++)
                        MMA_TF32(acc[mi][nj],
                                 __float_as_uint(af[mi].x), __float_as_uint(af[mi].y),
                                 __float_as_uint(af[mi].z), __float_as_uint(af[mi].w),
                                 b0, b1);
                }
            }
        }
    }

    float* Cp = C + (size_t)b * sCb;
#pragma unroll
    for (int mi = 0; mi < 4; mi++) {
        int r0 = m0 + (wy * 4 + mi) * 16 + q;
#pragma unroll
        for (int nj = 0; nj < 8; nj++) {
            int c0 = n0 + wx * 64 + nj * 8 + s * 2;
#pragma unroll
            for (int rr = 0; rr < 2; rr++) {
                int r = r0 + rr * 8;
                float v0 = acc[mi][nj][rr * 2], v1 = acc[mi][nj][rr * 2 + 1];
                if (BIASN) { v0 += bias[c0]; v1 += bias[c0 + 1]; }
                else       { float bv = bias[r]; v0 += bv; v1 += bv; }
                *reinterpret_cast<float2*>(&Cp[(size_t)r * ldc + c0]) = make_float2(v0, v1);
            }
        }
    }
}

// ---------------------------------------------------------------------------
// 128x128 GEMM (qk projection): 3-stage, ONE barrier per iter (distance 2).
// ---------------------------------------------------------------------------
#define PROJ_SMEM (3 * 32768)

__global__ __launch_bounds__(256, 2) void gemm_proj(
    const float* __restrict__ A, size_t sAb,
    const float* __restrict__ B, size_t sBb,
    const float* __restrict__ bias,
    float* __restrict__ C, size_t sCb, int ldc)
{
    extern __shared__ __align__(16) float sm[];
    const uint32_t smb = smem_u32(sm);
    const int b  = blockIdx.z;
    const int n0 = blockIdx.x * 128;
    const int m0 = blockIdx.y * 128;
    const float* Ag = A + (size_t)b * sAb + (size_t)(m0 >> 7) * 65536;
    const float* Bg = B + (size_t)b * sBb + (size_t)(n0 >> 7) * 65536;

    const int t = threadIdx.x, lane = t & 31, w = t >> 5;
    const int wm16 = (w & 3) * 2;
    const int wn8  = (w >> 2) * 8;
    const int q = lane >> 2, s = lane & 3;

    float acc[2][8][4] = {};

    auto fill = [&](int buf, int it) {
        const int ko = it * 32;
        const float* sa = Ag + (ko >> 3) * 1024;
        const float* sb = Bg + (ko >> 4) * 2048;
        uint32_t da = smb + buf * 32768 + t * 16;
#pragma unroll
        for (int i = 0; i < 4; i++) CP16(da + i * 4096, sa + t * 4 + i * 1024);
#pragma unroll
        for (int i = 0; i < 4; i++) CP16(da + 16384 + i * 4096, sb + t * 4 + i * 1024);
        CP_COMMIT();
    };

    fill(0, 0); fill(1, 1);
    int fb = 2;                            // next buffer to fill (it+2)%3

    for (int it = 0; it < 16; it++) {
        const int buf = it % 3;
        if (it == 15) CP_WAIT0();
        else CP_WAIT1();
        __syncthreads();
        if (it <= 13) { fill(fb, it + 2); fb = (fb == 2) ? 0 : fb + 1; }

        const float4* At = reinterpret_cast<const float4*>(sm) + buf * 2048;
        const float4* Bt = At + 1024;
#pragma unroll
        for (int kp = 0; kp < 2; kp++) {
            float4 af[2][2];
#pragma unroll
            for (int kkl = 0; kkl < 2; kkl++)
#pragma unroll
                for (int mi = 0; mi < 2; mi++)
                    af[mi][kkl] = At[((kp * 2 + kkl) * 8 + wm16 + mi) * 32 + lane];
#pragma unroll
            for (int nh = 0; nh < 2; nh++) {
                float4 bf[4];
#pragma unroll
                for (int nj = 0; nj < 4; nj++)
                    bf[nj] = Bt[(kp * 16 + wn8 + nh * 4 + nj) * 32 + lane];
#pragma unroll
                for (int kkl = 0; kkl < 2; kkl++)
#pragma unroll
                    for (int nj = 0; nj < 4; nj++) {
                        const int ni = nh * 4 + nj;
                        uint32_t b0 = __float_as_uint(kkl ? bf[nj].z : bf[nj].x);
                        uint32_t b1 = __float_as_uint(kkl ? bf[nj].w : bf[nj].y);
#pragma unroll
                        for (int mi = 0; mi < 2; mi++)
                            MMA_TF32(acc[mi][ni],
                                     __float_as_uint(af[mi][kkl].x),
                                     __float_as_uint(af[mi][kkl].y),
                                     __float_as_uint(af[mi][kkl].z),
                                     __float_as_uint(af[mi][kkl].w), b0, b1);
                    }
            }
        }
    }

    float* Cp = C + (size_t)b * sCb;
#pragma unroll
    for (int mi = 0; mi < 2; mi++) {
        int r0 = m0 + (wm16 + mi) * 16 + q;
#pragma unroll
        for (int ni = 0; ni < 8; ni++) {
            int c0 = n0 + (wn8 + ni) * 8 + s * 2;
#pragma unroll
            for (int rr = 0; rr < 2; rr++) {
                int r = r0 + rr * 8;
                float bv = bias[r];
                *reinterpret_cast<float2*>(&Cp[(size_t)r * ldc + c0]) =
                    make_float2(acc[mi][ni][rr * 2] + bv, acc[mi][ni][rr * 2 + 1] + bv);
            }
        }
    }
}

// ---------------------------------------------------------------- pre-passes
__global__ void round_w(const float* __restrict__ Wq, const float* __restrict__ bq,
                        const float* __restrict__ Wk, const float* __restrict__ bk,
                        const float* __restrict__ Wv, const float* __restrict__ Wo) {
    uint32_t idx = blockIdx.x * 256 + threadIdx.x;
    int job = blockIdx.y;
    if (job == 0) {
        if (idx < NC * NC) g_Wv32[idxA(idx >> 9, idx & 511)] = f2tf(Wv[idx]);
    } else if (job == 1) {
        if (idx < NC * NC) g_Wo32[idxB(idx >> 9, idx & 511)] = f2tf(Wo[idx]);
    } else {
        if (idx < 64 * NC) {
            uint32_t m = idx >> 9, c = idx & 511;
            g_Wqk[idxA(m, c)]      = f2tf(Wq[idx]);
            g_Wqk[idxA(m + 64, c)] = f2tf(Wk[idx]);
        }
        if (idx < 64) { g_bqk[idx] = bq[idx]; g_bqk[64 + idx] = bk[idx]; }
    }
}

__global__ __launch_bounds__(256) void transpose_x(const float* __restrict__ x) {
    __shared__ float ts[32][33];
    const int b = blockIdx.z;
    const int hw0 = blockIdx.x * 32, c0 = blockIdx.y * 32;
    const int tx = threadIdx.x, ty = threadIdx.y;
    const float* xb = x + (size_t)b * NC * NHW;
#pragma unroll
    for (int i = 0; i < 4; i++) {
        int r = ty + i * 8;
        ts[r][tx] = xb[(size_t)(c0 + r) * NHW + hw0 + tx];
    }
    __syncthreads();
    float* ob = g_xT + (size_t)b * NHW * NC;
#pragma unroll
    for (int i = 0; i < 4; i++) {
        int r = ty + i * 8;
        ob[idxB(hw0 + r, c0 + tx)] = f2tf(ts[tx][r]);
    }
}

// ---------------------------------------------------------------- scores+softmax
__global__ __launch_bounds__(256) void scores_kernel() {
    const int bn = blockIdx.x;
    const int b = bn >> 3, n = bn & 7;
    const float* qb = g_qk + (size_t)b * 128 * NHW + (size_t)n * 32768;
    const float* kb = qb + 64 * NHW;

    __shared__ float Qs[64][65];
    __shared__ float Ks[64][65];

    const int t = threadIdx.x;
    const int te = (t & 15) * 4;
    const int td = (t >> 4) * 4;

    float acc[4][4] = {};

    for (int lc = 0; lc < 8; lc++) {
#pragma unroll
        for (int i = 0; i < 16; i++) {
            int id = t + i * 256;
            Qs[id >> 6][id & 63] = qb[lc * 4096 + id];
            Ks[id >> 6][id & 63] = kb[lc * 4096 + id];
        }
        __syncthreads();
#pragma unroll 8
        for (int li = 0; li < 64; li++) {
            float a[4], bb[4];
#pragma unroll
            for (int i = 0; i < 4; i++) a[i] = Qs[li][td + i];
#pragma unroll
            for (int j = 0; j < 4; j++) bb[j] = Ks[li][te + j];
#pragma unroll
            for (int i = 0; i < 4; i++)
#pragma unroll
                for (int j = 0; j < 4; j++)
                    acc[i][j] = fmaf(a[i], bb[j], acc[i][j]);
        }
        __syncthreads();
    }

#pragma unroll
    for (int i = 0; i < 4; i++)
#pragma unroll
        for (int j = 0; j < 4; j++)
            Qs[td + i][te + j] = acc[i][j] * 0.125f;
    __syncthreads();

    if (t < 64) {
        float m = -1e30f;
        for (int e = 0; e < 64; e++) m = fmaxf(m, Qs[t][e]);
        float sum = 0.f;
        for (int e = 0; e < 64; e++) { float v2 = __expf(Qs[t][e] - m); Qs[t][e] = v2; sum += v2; }
        float inv = 1.f / sum;
        for (int e = 0; e < 64; e++) Qs[t][e] *= inv;
    }
    __syncthreads();

    float* ab = g_attn + (size_t)bn * 4096;
#pragma unroll
    for (int i = 0; i < 16; i++) {
        int id = t + i * 256;
        ab[id] = Qs[id >> 6][id & 63];
    }
}

// ---------------------------------------------------------------- attn @ v (TC)
// Split-precision tf32 (Vhi*Ahi + Vhi*Alo + Vlo*Ahi). Output -> g_mid idxA.
#define AVS 4352   // 64*68 floats per tile
#define ATTNV_SMEM (3 * AVS * 4)

__global__ __launch_bounds__(256) void attnv_tc() {
    extern __shared__ __align__(16) float sm[];
    const uint32_t smb = smem_u32(sm);
    const int d2 = blockIdx.x * 2;
    const int n  = blockIdx.y;
    const int b  = blockIdx.z;
    const int t = threadIdx.x, lane = t & 31, w = t >> 5;
    const int q = lane >> 2, s = lane & 3;

    {
        const float* srcs[3] = {
            g_attn + ((size_t)b * 8 + n) * 4096,
            g_v + ((size_t)b * NC + n * 64 + d2) * (size_t)NHW,
            g_v + ((size_t)b * NC + n * 64 + d2 + 1) * (size_t)NHW };
#pragma unroll
        for (int tile = 0; tile < 3; tile++) {
#pragma unroll
            for (int i = 0; i < 4; i++) {
                int unit = t + i * 256;
                int row = unit >> 4, ch4 = (unit & 15) * 4;
                CP16(smb + (tile * AVS + row * 68 + ch4) * 4,
                     srcs[tile] + row * 64 + ch4);
            }
        }
        CP_COMMIT(); CP_WAIT0();
    }
    __syncthreads();

    const float* At = sm;
    const float* Vt = sm + AVS + (w & 1) * AVS;
    const int rbase = (w >> 1) * 16;

    float acc[8][4] = {};
#pragma unroll
    for (int kb = 0; kb < 8; kb++) {
        const int k8 = kb * 8;
        const int rb = rbase + q;
        float av[4];
        av[0] = Vt[rb * 68 + k8 + s];
        av[1] = Vt[(rb + 8) * 68 + k8 + s];
        av[2] = Vt[rb * 68 + k8 + s + 4];
        av[3] = Vt[(rb + 8) * 68 + k8 + s + 4];
        uint32_t ah[4], al[4];
#pragma unroll
        for (int i = 0; i < 4; i++) {
            float h = f2tf(av[i]);
            ah[i] = __float_as_uint(h);
            al[i] = __float_as_uint(f2tf(av[i] - h));
        }
#pragma unroll
        for (int nb = 0; nb < 8; nb++) {
            float bv0 = At[(nb * 8 + q) * 68 + k8 + s];
            float bv1 = At[(nb * 8 + q) * 68 + k8 + s + 4];
            float bh0f = f2tf(bv0), bh1f = f2tf(bv1);
            uint32_t bh0 = __float_as_uint(bh0f), bh1 = __float_as_uint(bh1f);
            uint32_t bl0 = __float_as_uint(f2tf(bv0 - bh0f));
            uint32_t bl1 = __float_as_uint(f2tf(bv1 - bh1f));
            MMA_TF32(acc[nb], ah[0], ah[1], ah[2], ah[3], bh0, bh1);
            MMA_TF32(acc[nb], ah[0], ah[1], ah[2], ah[3], bl0, bl1);
            MMA_TF32(acc[nb], al[0], al[1], al[2], al[3], bh0, bh1);
        }
    }

    const int ch_out = (d2 + (w & 1)) * 8 + n;
    float* mb = g_mid + (size_t)b * NC * NHW;
#pragma unroll
    for (int nb = 0; nb < 8; nb++)
#pragma unroll
        for (int rr = 0; rr < 2; rr++) {
            const int h = rbase + q + rr * 8;
            const uint32_t r = ch_out * 8 + (h >> 3);
            const uint32_t kc0 = (h & 7) * 64 + nb * 8 + s * 2;
#pragma unroll
            for (int j = 0; j < 2; j++)
                mb[idxA(r, kc0 + j)] = f2tf(acc[nb][rr * 2 + j]);
        }
}

// ---------------------------------------------------------------- launch
extern "C" void kernel_launch(void* const* d_in, const int* in_sizes, int n_in,
                              void* d_out, int out_size) {
    (void)in_sizes; (void)n_in; (void)out_size;
    const float* x  = (const float*)d_in[0];
    const float* Wq = (const float*)d_in[1];
    const float* bq = (const float*)d_in[2];
    const float* Wk = (const float*)d_in[3];
    const float* bk = (const float*)d_in[4];
    const float* Wv = (const float*)d_in[5];
    const float* bv = (const float*)d_in[6];
    const float* Wo = (const float*)d_in[7];
    const float* bo = (const float*)d_in[8];
    float* out = (float*)d_out;

    cudaFuncSetAttribute(gemm_proj, cudaFuncAttributeMaxDynamicSharedMemorySize, PROJ_SMEM);
    cudaFuncSetAttribute(gemm_big<false>, cudaFuncAttributeMaxDynamicSharedMemorySize, BIG_SMEM);
    cudaFuncSetAttribute(gemm_big<true>,  cudaFuncAttributeMaxDynamicSharedMemorySize, BIG_SMEM);
    cudaFuncSetAttribute(attnv_tc,  cudaFuncAttributeMaxDynamicSharedMemorySize, ATTNV_SMEM);

    float *xT, *qk_p, *v_p, *mid_p, *Wqk_p, *Wv_p, *Wo_p, *bqk_p;
    cudaGetSymbolAddress((void**)&xT,    g_xT);
    cudaGetSymbolAddress((void**)&qk_p,  g_qk);
    cudaGetSymbolAddress((void**)&v_p,   g_v);
    cudaGetSymbolAddress((void**)&mid_p, g_mid);
    cudaGetSymbolAddress((void**)&Wqk_p, g_Wqk);
    cudaGetSymbolAddress((void**)&Wv_p,  g_Wv32);
    cudaGetSymbolAddress((void**)&Wo_p,  g_Wo32);
    cudaGetSymbolAddress((void**)&bqk_p, g_bqk);

    round_w<<<dim3(1024, 3), 256>>>(Wq, bq, Wk, bk, Wv, Wo);
    transpose_x<<<dim3(128, 16, 16), dim3(32, 8)>>>(x);

    // q/k projection: C[128 x 4096] per b
    gemm_proj<<<dim3(32, 1, NB), 256, PROJ_SMEM>>>(
        Wqk_p, 0, xT, (size_t)NHW * NC, bqk_p,
        qk_p, (size_t)128 * NHW, NHW);
    // v projection: C[512 x 4096] per b
    gemm_big<false><<<dim3(32, 2, NB), 256, BIG_SMEM>>>(
        Wv_p, 0, xT, (size_t)NHW * NC, bv,
        v_p, (size_t)NC * NHW, NHW);

    scores_kernel<<<128, 256>>>();
    attnv_tc<<<dim3(32, 8, NB), 256, ATTNV_SMEM>>>();

    // final linear: C[4096 x 512] per b
    gemm_big<true><<<dim3(4, 16, NB), 256, BIG_SMEM>>>(
        mid_p, (size_t)NC * NHW, Wo_p, 0, bo,
        out, (size_t)NC * NHW, NC);
}

// round 15
// speedup vs baseline: 1.0383x; 1.0383x over previous
#include <cuda_runtime.h>
#include <cstdint>

#define NB 16
#define NC 512
#define NHW 4096
#define KDIM 512

// ---------------------------------------------------------------- scratch
__device__ float g_xT[(size_t)NB * NHW * NC];    // B-fragment layout (n=hw,k=c)
__device__ float g_qk[(size_t)NB * 128 * NHW];   // row-major
__device__ float g_v[(size_t)NB * NC * NHW];     // row-major
__device__ float g_attn[(size_t)NB * 8 * 64 * 64];
__device__ float g_mid[(size_t)NB * NC * NHW];   // A-fragment layout, tf32
__device__ float g_Wqk[128 * NC];                // A-fragment layout
__device__ float g_Wv32[NC * NC];                // A-fragment layout
__device__ float g_Wo32[NC * NC];                // B-fragment layout
__device__ float g_bqk[128];

__device__ __forceinline__ float f2tf(float f) {
    uint32_t o; asm("cvt.rna.tf32.f32 %0, %1;" : "=r"(o) : "f"(f));
    return __uint_as_float(o);
}

// A-fragment-major: 16m x 8k blocks, ordered [M128][kb8][mb16][lane][slot]
__device__ __forceinline__ uint32_t idxA(uint32_t m, uint32_t k) {
    return ((((m >> 7) * (KDIM / 8) + (k >> 3)) * 8 + ((m & 127) >> 4)) * 32
            + (((m & 7) << 2) | (k & 3))) * 4
           + (((m >> 3) & 1) | (((k >> 2) & 1) << 1));
}
// B-fragment-major: 8n x 16k blocks, ordered [N128][kb16][nb8][lane][slot]
__device__ __forceinline__ uint32_t idxB(uint32_t n, uint32_t k) {
    return ((((n >> 7) * (KDIM / 16) + (k >> 4)) * 16 + ((n & 127) >> 3)) * 32
            + (((n & 7) << 2) | (k & 3))) * 4
           + ((k >> 2) & 3);
}

#define CP16(dst, src) asm volatile("cp.async.cg.shared.global [%0], [%1], 16;" :: "r"(dst), "l"(src) : "memory")
#define CP_COMMIT()    asm volatile("cp.async.commit_group;" ::: "memory")
#define CP_WAIT2()     asm volatile("cp.async.wait_group 2;" ::: "memory")
#define CP_WAIT1()     asm volatile("cp.async.wait_group 1;" ::: "memory")
#define CP_WAIT0()     asm volatile("cp.async.wait_group 0;" ::: "memory")

__device__ __forceinline__ uint32_t smem_u32(const void* p) {
    uint32_t a;
    asm("{ .reg .u64 t; cvta.to.shared.u64 t, %1; cvt.u32.u64 %0, t; }" : "=r"(a) : "l"(p));
    return a;
}

#define MMA_TF32(acc, a0, a1, a2, a3, b0, b1) \
    asm volatile("mma.sync.aligned.m16n8k8.row.col.f32.tf32.tf32.f32 " \
        "{%0,%1,%2,%3},{%4,%5,%6,%7},{%8,%9},{%0,%1,%2,%3};" \
        : "+f"((acc)[0]), "+f"((acc)[1]), "+f"((acc)[2]), "+f"((acc)[3]) \
        : "r"(a0), "r"(a1), "r"(a2), "r"(a3), "r"(b0), "r"(b1))

// ---------------------------------------------------------------------------
// Big-tile GEMM: CTA 256m x 128n, warp tile 64x64 (8 warps), BK=32,
// 3-stage cp.async (R13-proven schedule).
// C[m][n] = sum_k A[m][k]*B[n][k] + bias (m if !BIASN else n).
// ---------------------------------------------------------------------------
#define BIG_STAGE_B 49152                 // A 32KB + B 16KB
#define BIG_SMEM (3 * BIG_STAGE_B)

template <bool BIASN>
__global__ __launch_bounds__(256, 1) void gemm_big(
    const float* __restrict__ A, size_t sAb,
    const float* __restrict__ B, size_t sBb,
    const float* __restrict__ bias,
    float* __restrict__ C, size_t sCb, int ldc)
{
    extern __shared__ __align__(16) float sm[];
    const uint32_t smb = smem_u32(sm);
    const int b  = blockIdx.z;
    const int n0 = blockIdx.x * 128;
    const int m0 = blockIdx.y * 256;
    const float* Ag = A + (size_t)b * sAb + (size_t)(m0 >> 7) * 65536;
    const float* Bg = B + (size_t)b * sBb + (size_t)(n0 >> 7) * 65536;

    const int t = threadIdx.x, lane = t & 31, w = t >> 5;
    const int wy = w & 3, wx = w >> 2;
    const int blk = wy >> 1, mb0 = (wy & 1) * 4;
    const int q = lane >> 2, s = lane & 3;

    float acc[4][8][4] = {};

    auto fill = [&](int buf, int it) {
        const int ko = it * 32;
        const float* a0 = Ag + (ko >> 3) * 1024;
        const float* a1 = a0 + 65536;
        const float* bb = Bg + (ko >> 4) * 2048;
        uint32_t d = smb + buf * BIG_STAGE_B + t * 16;
#pragma unroll
        for (int i = 0; i < 4; i++) CP16(d + i * 4096,         a0 + t * 4 + i * 1024);
#pragma unroll
        for (int i = 0; i < 4; i++) CP16(d + 16384 + i * 4096, a1 + t * 4 + i * 1024);
#pragma unroll
        for (int i = 0; i < 4; i++) CP16(d + 32768 + i * 4096, bb + t * 4 + i * 1024);
        CP_COMMIT();
    };

    fill(0, 0); fill(1, 1);
    int fb = 2;

    for (int it = 0; it < 16; it++) {
        const int buf = it % 3;
        __syncthreads();
        if (it <= 13) { fill(fb, it + 2); fb = (fb == 2) ? 0 : fb + 1; CP_WAIT2(); }
        else if (it == 14) CP_WAIT1();
        else CP_WAIT0();
        __syncthreads();

        const float4* At = reinterpret_cast<const float4*>(sm) + buf * 3072;
        const float4* Bt = At + 2048;
#pragma unroll
        for (int kp = 0; kp < 2; kp++) {
            float4 bf[8];
#pragma unroll
            for (int nj = 0; nj < 8; nj++)
                bf[nj] = Bt[(kp * 16 + wx * 8 + nj) * 32 + lane];
#pragma unroll
            for (int kkl = 0; kkl < 2; kkl++) {
                const int kb = kp * 2 + kkl;
                float4 af[4];
#pragma unroll
                for (int mi = 0; mi < 4; mi++)
                    af[mi] = At[blk * 1024 + (kb * 8 + mb0 + mi) * 32 + lane];
#pragma unroll
                for (int nj = 0; nj < 8; nj++) {
                    uint32_t b0 = __float_as_uint(kkl ? bf[nj].z : bf[nj].x);
                    uint32_t b1 = __float_as_uint(kkl ? bf[nj].w : bf[nj].y);
#pragma unroll
                    for (int mi = 0; mi < 4; mi++)
                        MMA_TF32(acc[mi][nj],
                                 __float_as_uint(af[mi].x), __float_as_uint(af[mi].y),
                                 __float_as_uint(af[mi].z), __float_as_uint(af[mi].w),
                                 b0, b1);
                }
            }
        }
    }

    float* Cp = C + (size_t)b * sCb;
#pragma unroll
    for (int mi = 0; mi < 4; mi++) {
        int r0 = m0 + (wy * 4 + mi) * 16 + q;
#pragma unroll
        for (int nj = 0; nj < 8; nj++) {
            int c0 = n0 + wx * 64 + nj * 8 + s * 2;
#pragma unroll
            for (int rr = 0; rr < 2; rr++) {
                int r = r0 + rr * 8;
                float v0 = acc[mi][nj][rr * 2], v1 = acc[mi][nj][rr * 2 + 1];
                if (BIASN) { v0 += bias[c0]; v1 += bias[c0 + 1]; }
                else       { float bv = bias[r]; v0 += bv; v1 += bv; }
                *reinterpret_cast<float2*>(&Cp[(size_t)r * ldc + c0]) = make_float2(v0, v1);
            }
        }
    }
}

// ---------------------------------------------------------------------------
// 128x128 GEMM (qk projection), R13-proven schedule.
// ---------------------------------------------------------------------------
#define PROJ_SMEM (3 * 32768)

__global__ __launch_bounds__(256, 2) void gemm_proj(
    const float* __restrict__ A, size_t sAb,
    const float* __restrict__ B, size_t sBb,
    const float* __restrict__ bias,
    float* __restrict__ C, size_t sCb, int ldc)
{
    extern __shared__ __align__(16) float sm[];
    const uint32_t smb = smem_u32(sm);
    const int b  = blockIdx.z;
    const int n0 = blockIdx.x * 128;
    const int m0 = blockIdx.y * 128;
    const float* Ag = A + (size_t)b * sAb + (size_t)(m0 >> 7) * 65536;
    const float* Bg = B + (size_t)b * sBb + (size_t)(n0 >> 7) * 65536;

    const int t = threadIdx.x, lane = t & 31, w = t >> 5;
    const int wm16 = (w & 3) * 2;
    const int wn8  = (w >> 2) * 8;
    const int q = lane >> 2, s = lane & 3;

    float acc[2][8][4] = {};

    auto fill = [&](int buf, int it) {
        const int ko = it * 32;
        const float* sa = Ag + (ko >> 3) * 1024;
        const float* sb = Bg + (ko >> 4) * 2048;
        uint32_t da = smb + buf * 32768 + t * 16;
#pragma unroll
        for (int i = 0; i < 4; i++) CP16(da + i * 4096, sa + t * 4 + i * 1024);
#pragma unroll
        for (int i = 0; i < 4; i++) CP16(da + 16384 + i * 4096, sb + t * 4 + i * 1024);
        CP_COMMIT();
    };

    fill(0, 0); fill(1, 1);
    int fb = 2;

    for (int it = 0; it < 16; it++) {
        const int buf = it % 3;
        __syncthreads();
        if (it <= 13) { fill(fb, it + 2); fb = (fb == 2) ? 0 : fb + 1; CP_WAIT2(); }
        else if (it == 14) CP_WAIT1();
        else CP_WAIT0();
        __syncthreads();

        const float4* At = reinterpret_cast<const float4*>(sm) + buf * 2048;
        const float4* Bt = At + 1024;
#pragma unroll
        for (int kp = 0; kp < 2; kp++) {
            float4 af[2][2];
#pragma unroll
            for (int kkl = 0; kkl < 2; kkl++)
#pragma unroll
                for (int mi = 0; mi < 2; mi++)
                    af[mi][kkl] = At[((kp * 2 + kkl) * 8 + wm16 + mi) * 32 + lane];
#pragma unroll
            for (int nh = 0; nh < 2; nh++) {
                float4 bf[4];
#pragma unroll
                for (int nj = 0; nj < 4; nj++)
                    bf[nj] = Bt[(kp * 16 + wn8 + nh * 4 + nj) * 32 + lane];
#pragma unroll
                for (int kkl = 0; kkl < 2; kkl++)
#pragma unroll
                    for (int nj = 0; nj < 4; nj++) {
                        const int ni = nh * 4 + nj;
                        uint32_t b0 = __float_as_uint(kkl ? bf[nj].z : bf[nj].x);
                        uint32_t b1 = __float_as_uint(kkl ? bf[nj].w : bf[nj].y);
#pragma unroll
                        for (int mi = 0; mi < 2; mi++)
                            MMA_TF32(acc[mi][ni],
                                     __float_as_uint(af[mi][kkl].x),
                                     __float_as_uint(af[mi][kkl].y),
                                     __float_as_uint(af[mi][kkl].z),
                                     __float_as_uint(af[mi][kkl].w), b0, b1);
                    }
            }
        }
    }

    float* Cp = C + (size_t)b * sCb;
#pragma unroll
    for (int mi = 0; mi < 2; mi++) {
        int r0 = m0 + (wm16 + mi) * 16 + q;
#pragma unroll
        for (int ni = 0; ni < 8; ni++) {
            int c0 = n0 + (wn8 + ni) * 8 + s * 2;
#pragma unroll
            for (int rr = 0; rr < 2; rr++) {
                int r = r0 + rr * 8;
                float bv = bias[r];
                *reinterpret_cast<float2*>(&Cp[(size_t)r * ldc + c0]) =
                    make_float2(acc[mi][ni][rr * 2] + bv, acc[mi][ni][rr * 2 + 1] + bv);
            }
        }
    }
}

// ---------------------------------------------------------------- pre-passes
__global__ void round_w(const float* __restrict__ Wq, const float* __restrict__ bq,
                        const float* __restrict__ Wk, const float* __restrict__ bk,
                        const float* __restrict__ Wv, const float* __restrict__ Wo) {
    uint32_t idx = blockIdx.x * 256 + threadIdx.x;
    int job = blockIdx.y;
    if (job == 0) {
        if (idx < NC * NC) g_Wv32[idxA(idx >> 9, idx & 511)] = f2tf(Wv[idx]);
    } else if (job == 1) {
        if (idx < NC * NC) g_Wo32[idxB(idx >> 9, idx & 511)] = f2tf(Wo[idx]);
    } else {
        if (idx < 64 * NC) {
            uint32_t m = idx >> 9, c = idx & 511;
            g_Wqk[idxA(m, c)]      = f2tf(Wq[idx]);
            g_Wqk[idxA(m + 64, c)] = f2tf(Wk[idx]);
        }
        if (idx < 64) { g_bqk[idx] = bq[idx]; g_bqk[64 + idx] = bk[idx]; }
    }
}

__global__ __launch_bounds__(256) void transpose_x(const float* __restrict__ x) {
    __shared__ float ts[32][33];
    const int b = blockIdx.z;
    const int hw0 = blockIdx.x * 32, c0 = blockIdx.y * 32;
    const int tx = threadIdx.x, ty = threadIdx.y;
    const float* xb = x + (size_t)b * NC * NHW;
#pragma unroll
    for (int i = 0; i < 4; i++) {
        int r = ty + i * 8;
        ts[r][tx] = xb[(size_t)(c0 + r) * NHW + hw0 + tx];
    }
    __syncthreads();
    float* ob = g_xT + (size_t)b * NHW * NC;
#pragma unroll
    for (int i = 0; i < 4; i++) {
        int r = ty + i * 8;
        ob[idxB(hw0 + r, c0 + tx)] = f2tf(ts[tx][r]);
    }
}

// ---------------------------------------------------------------- scores+softmax
__global__ __launch_bounds__(256) void scores_kernel() {
    const int bn = blockIdx.x;
    const int b = bn >> 3, n = bn & 7;
    const float* qb = g_qk + (size_t)b * 128 * NHW + (size_t)n * 32768;
    const float* kb = qb + 64 * NHW;

    __shared__ float Qs[64][65];
    __shared__ float Ks[64][65];

    const int t = threadIdx.x;
    const int te = (t & 15) * 4;
    const int td = (t >> 4) * 4;

    float acc[4][4] = {};

    for (int lc = 0; lc < 8; lc++) {
#pragma unroll
        for (int i = 0; i < 16; i++) {
            int id = t + i * 256;
            Qs[id >> 6][id & 63] = qb[lc * 4096 + id];
            Ks[id >> 6][id & 63] = kb[lc * 4096 + id];
        }
        __syncthreads();
#pragma unroll 8
        for (int li = 0; li < 64; li++) {
            float a[4], bb[4];
#pragma unroll
            for (int i = 0; i < 4; i++) a[i] = Qs[li][td + i];
#pragma unroll
            for (int j = 0; j < 4; j++) bb[j] = Ks[li][te + j];
#pragma unroll
            for (int i = 0; i < 4; i++)
#pragma unroll
                for (int j = 0; j < 4; j++)
                    acc[i][j] = fmaf(a[i], bb[j], acc[i][j]);
        }
        __syncthreads();
    }

#pragma unroll
    for (int i = 0; i < 4; i++)
#pragma unroll
        for (int j = 0; j < 4; j++)
            Qs[td + i][te + j] = acc[i][j] * 0.125f;
    __syncthreads();

    if (t < 64) {
        float m = -1e30f;
        for (int e = 0; e < 64; e++) m = fmaxf(m, Qs[t][e]);
        float sum = 0.f;
        for (int e = 0; e < 64; e++) { float v2 = __expf(Qs[t][e] - m); Qs[t][e] = v2; sum += v2; }
        float inv = 1.f / sum;
        for (int e = 0; e < 64; e++) Qs[t][e] *= inv;
    }
    __syncthreads();

    float* ab = g_attn + (size_t)bn * 4096;
#pragma unroll
    for (int i = 0; i < 16; i++) {
        int id = t + i * 256;
        ab[id] = Qs[id >> 6][id & 63];
    }
}

// ---------------------------------------------------------------- attn @ v (TC)
// Split-precision tf32 (Vhi*Ahi + Vhi*Alo + Vlo*Ahi). Output -> g_mid idxA.
#define AVS 4352   // 64*68 floats per tile
#define ATTNV_SMEM (3 * AVS * 4)

__global__ __launch_bounds__(256) void attnv_tc() {
    extern __shared__ __align__(16) float sm[];
    const uint32_t smb = smem_u32(sm);
    const int d2 = blockIdx.x * 2;
    const int n  = blockIdx.y;
    const int b  = blockIdx.z;
    const int t = threadIdx.x, lane = t & 31, w = t >> 5;
    const int q = lane >> 2, s = lane & 3;

    {
        const float* srcs[3] = {
            g_attn + ((size_t)b * 8 + n) * 4096,
            g_v + ((size_t)b * NC + n * 64 + d2) * (size_t)NHW,
            g_v + ((size_t)b * NC + n * 64 + d2 + 1) * (size_t)NHW };
#pragma unroll
        for (int tile = 0; tile < 3; tile++) {
#pragma unroll
            for (int i = 0; i < 4; i++) {
                int unit = t + i * 256;
                int row = unit >> 4, ch4 = (unit & 15) * 4;
                CP16(smb + (tile * AVS + row * 68 + ch4) * 4,
                     srcs[tile] + row * 64 + ch4);
            }
        }
        CP_COMMIT(); CP_WAIT0();
    }
    __syncthreads();

    const float* At = sm;
    const float* Vt = sm + AVS + (w & 1) * AVS;
    const int rbase = (w >> 1) * 16;

    float acc[8][4] = {};
#pragma unroll
    for (int kb = 0; kb < 8; kb++) {
        const int k8 = kb * 8;
        const int rb = rbase + q;
        float av[4];
        av[0] = Vt[rb * 68 + k8 + s];
        av[1] = Vt[(rb + 8) * 68 + k8 + s];
        av[2] = Vt[rb * 68 + k8 + s + 4];
        av[3] = Vt[(rb + 8) * 68 + k8 + s + 4];
        uint32_t ah[4], al[4];
#pragma unroll
        for (int i = 0; i < 4; i++) {
            float h = f2tf(av[i]);
            ah[i] = __float_as_uint(h);
            al[i] = __float_as_uint(f2tf(av[i] - h));
        }
#pragma unroll
        for (int nb = 0; nb < 8; nb++) {
            float bv0 = At[(nb * 8 + q) * 68 + k8 + s];
            float bv1 = At[(nb * 8 + q) * 68 + k8 + s + 4];
            float bh0f = f2tf(bv0), bh1f = f2tf(bv1);
            uint32_t bh0 = __float_as_uint(bh0f), bh1 = __float_as_uint(bh1f);
            uint32_t bl0 = __float_as_uint(f2tf(bv0 - bh0f));
            uint32_t bl1 = __float_as_uint(f2tf(bv1 - bh1f));
            MMA_TF32(acc[nb], ah[0], ah[1], ah[2], ah[3], bh0, bh1);
            MMA_TF32(acc[nb], ah[0], ah[1], ah[2], ah[3], bl0, bl1);
            MMA_TF32(acc[nb], al[0], al[1], al[2], al[3], bh0, bh1);
        }
    }

    const int ch_out = (d2 + (w & 1)) * 8 + n;
    float* mb = g_mid + (size_t)b * NC * NHW;
#pragma unroll
    for (int nb = 0; nb < 8; nb++)
#pragma unroll
        for (int rr = 0; rr < 2; rr++) {
            const int h = rbase + q + rr * 8;
            const uint32_t r = ch_out * 8 + (h >> 3);
            const uint32_t kc0 = (h & 7) * 64 + nb * 8 + s * 2;
#pragma unroll
            for (int j = 0; j < 2; j++)
                mb[idxA(r, kc0 + j)] = f2tf(acc[nb][rr * 2 + j]);
        }
}

// ---------------------------------------------------------------- launch
extern "C" void kernel_launch(void* const* d_in, const int* in_sizes, int n_in,
                              void* d_out, int out_size) {
    (void)in_sizes; (void)n_in; (void)out_size;
    const float* x  = (const float*)d_in[0];
    const float* Wq = (const float*)d_in[1];
    const float* bq = (const float*)d_in[2];
    const float* Wk = (const float*)d_in[3];
    const float* bk = (const float*)d_in[4];
    const float* Wv = (const float*)d_in[5];
    const float* bv = (const float*)d_in[6];
    const float* Wo = (const float*)d_in[7];
    const float* bo = (const float*)d_in[8];
    float* out = (float*)d_out;

    cudaFuncSetAttribute(gemm_proj, cudaFuncAttributeMaxDynamicSharedMemorySize, PROJ_SMEM);
    cudaFuncSetAttribute(gemm_big<false>, cudaFuncAttributeMaxDynamicSharedMemorySize, BIG_SMEM);
    cudaFuncSetAttribute(gemm_big<true>,  cudaFuncAttributeMaxDynamicSharedMemorySize, BIG_SMEM);
    cudaFuncSetAttribute(attnv_tc,  cudaFuncAttributeMaxDynamicSharedMemorySize, ATTNV_SMEM);

    float *xT, *qk_p, *v_p, *mid_p, *Wqk_p, *Wv_p, *Wo_p, *bqk_p;
    cudaGetSymbolAddress((void**)&xT,    g_xT);
    cudaGetSymbolAddress((void**)&qk_p,  g_qk);
    cudaGetSymbolAddress((void**)&v_p,   g_v);
    cudaGetSymbolAddress((void**)&mid_p, g_mid);
    cudaGetSymbolAddress((void**)&Wqk_p, g_Wqk);
    cudaGetSymbolAddress((void**)&Wv_p,  g_Wv32);
    cudaGetSymbolAddress((void**)&Wo_p,  g_Wo32);
    cudaGetSymbolAddress((void**)&bqk_p, g_bqk);

    // Side stream + fork/join events (created once; resources, not work).
    static cudaStream_t s2 = nullptr;
    static cudaEvent_t e_t = nullptr, e_w = nullptr, e_s = nullptr;
    if (!s2) {
        cudaStreamCreateWithFlags(&s2, cudaStreamNonBlocking);
        cudaEventCreateWithFlags(&e_t, cudaEventDisableTiming);
        cudaEventCreateWithFlags(&e_w, cudaEventDisableTiming);
        cudaEventCreateWithFlags(&e_s, cudaEventDisableTiming);
    }

    // Fork: round_w on s2 concurrent with transpose_x on main.
    cudaEventRecord(e_t, 0);                       // fork point: s2 joins capture
    cudaStreamWaitEvent(s2, e_t, 0);
    round_w<<<dim3(1024, 3), 256, 0, s2>>>(Wq, bq, Wk, bk, Wv, Wo);
    transpose_x<<<dim3(128, 16, 16), dim3(32, 8)>>>(x);

    // Cross edges: s2's qk-proj needs transpose_x; main's v-proj needs round_w.
    cudaEventRecord(e_t, 0);
    cudaStreamWaitEvent(s2, e_t, 0);
    cudaEventRecord(e_w, s2);
    cudaStreamWaitEvent(0, e_w, 0);

    // s2: qk projection then scores (overlaps with main's v projection).
    gemm_proj<<<dim3(32, 1, NB), 256, PROJ_SMEM, s2>>>(
        Wqk_p, 0, xT, (size_t)NHW * NC, bqk_p,
        qk_p, (size_t)128 * NHW, NHW);
    scores_kernel<<<128, 256, 0, s2>>>();
    cudaEventRecord(e_s, s2);

    // main: v projection
    gemm_big<false><<<dim3(32, 2, NB), 256, BIG_SMEM>>>(
        Wv_p, 0, xT, (size_t)NHW * NC, bv,
        v_p, (size_t)NC * NHW, NHW);

    // join: attnv needs v (main) + attn (s2)
    cudaStreamWaitEvent(0, e_s, 0);
    attnv_tc<<<dim3(32, 8, NB), 256, ATTNV_SMEM>>>();

    // final linear
    gemm_big<true><<<dim3(4, 16, NB), 256, BIG_SMEM>>>(
        mid_p, (size_t)NC * NHW, Wo_p, 0, bo,
        out, (size_t)NC * NHW, NC);
}